// round 5
// baseline (speedup 1.0000x reference)
#include <cuda_runtime.h>

#define B_  64
#define F_  256
#define T_  1024
#define H_  1024
#define O_  512

#define GRC   128         // recurrence CTAs (one wave)
#define CPC   32          // cols per CTA (32 col-groups)
#define RPC   16          // batch rows per CTA (4 batch-quarters)
#define KSPL  16          // k-split (warp = one k-slice of 64)
#define KPT   64          // k per warp-slice
#define WST   1028        // smem stride (floats): bank offset 4, 16B aligned
#define RST   520         // reduce buffer row stride (per k-slice)

// -------- scratch (no allocations allowed; device globals) --------
__device__ float g_xT[(size_t)T_ * B_ * F_];
__device__ float g_pre[(size_t)T_ * B_ * H_];       // (T,B,H)
__device__ float g_states[(size_t)B_ * T_ * H_];    // (B,T,H)
__device__ float g_s[2][B_ * H_];
__device__ unsigned g_bar;

typedef unsigned long long ull;
union F2U { ull u; float2 f; };

__device__ __forceinline__ void fma2(ull& d, ull a, ull b) {
    asm("fma.rn.f32x2 %0, %1, %2, %0;" : "+l"(d) : "l"(a), "l"(b));
}

// ---------------- init: zero state buffer 0 + barrier ----------------
__global__ void k_init() {
    int idx = blockIdx.x * blockDim.x + threadIdx.x;
    for (int i = idx; i < B_ * H_; i += gridDim.x * blockDim.x) g_s[0][i] = 0.0f;
    if (idx == 0) g_bar = 0u;
}

// ---------------- transpose x(B,F,T) -> xT(T*B, F) ----------------
__global__ void k_transpose(const float* __restrict__ x) {
    __shared__ float tile[32][33];
    int b  = blockIdx.z;
    int f0 = blockIdx.y * 32;
    int t0 = blockIdx.x * 32;
    int tx = threadIdx.x, ty = threadIdx.y;     // 32 x 8
#pragma unroll
    for (int i = 0; i < 4; i++) {
        int f = f0 + ty + i * 8;
        tile[ty + i * 8][tx] = x[((size_t)b * F_ + f) * T_ + t0 + tx];
    }
    __syncthreads();
#pragma unroll
    for (int i = 0; i < 4; i++) {
        int t = t0 + ty + i * 8;
        g_xT[((size_t)t * B_ + b) * F_ + f0 + tx] = tile[tx][ty + i * 8];
    }
}

// ---------------- fp32 SGEMM with f32x2 packed FMA ----------------
// Tiles 128x64x16, 256 thr, 8x4/thread. Inner loop unrolled over 2 k-pairs
// with 16B LDS (stride 20 floats keeps them 16B-aligned) -> halves LDS
// wavefronts per FMA2 so the kernel is FMA-bound, not crossbar-bound.
__global__ void __launch_bounds__(256) k_sgemm(const float* __restrict__ A,
                                               const float* __restrict__ Bm,
                                               const float* __restrict__ bias,
                                               float* __restrict__ C,
                                               int M, int N, int K) {
    __shared__ __align__(16) float As[128 * 20];
    __shared__ __align__(16) float Bs[64 * 20];
    int tid = threadIdx.x;
    int tx = tid & 15, ty = tid >> 4;
    int n0 = blockIdx.x * 64;
    int m0 = blockIdx.y * 128;

    ull acc[8][4];
#pragma unroll
    for (int i = 0; i < 8; i++)
#pragma unroll
        for (int j = 0; j < 4; j++) acc[i][j] = 0ull;

    for (int k0 = 0; k0 < K; k0 += 16) {
        // A tile: 128 rows x 16 k -> As[row][k] (stride 20, float4 stores)
#pragma unroll
        for (int l = 0; l < 2; l++) {
            int j = tid + l * 256;
            int row = j >> 2, kq = (j & 3) * 4;
            float4 v = *reinterpret_cast<const float4*>(&A[(size_t)(m0 + row) * K + k0 + kq]);
            *reinterpret_cast<float4*>(&As[row * 20 + kq]) = v;
        }
        // B tile: 16 k x 64 n -> Bs[n][k] (transposed, stride 20)
        {
            int k = tid >> 4, nq = (tid & 15) * 4;
            float4 v = *reinterpret_cast<const float4*>(&Bm[(size_t)(k0 + k) * N + n0 + nq]);
            Bs[(nq + 0) * 20 + k] = v.x;
            Bs[(nq + 1) * 20 + k] = v.y;
            Bs[(nq + 2) * 20 + k] = v.z;
            Bs[(nq + 3) * 20 + k] = v.w;
        }
        __syncthreads();
#pragma unroll
        for (int p = 0; p < 8; p += 2) {            // 2 k-pairs per iter
            ulonglong2 a4[8], b4[4];
#pragma unroll
            for (int i = 0; i < 8; i++)
                a4[i] = *reinterpret_cast<const ulonglong2*>(&As[(ty * 8 + i) * 20 + p * 2]);
#pragma unroll
            for (int j = 0; j < 4; j++)
                b4[j] = *reinterpret_cast<const ulonglong2*>(&Bs[(tx * 4 + j) * 20 + p * 2]);
#pragma unroll
            for (int i = 0; i < 8; i++)
#pragma unroll
                for (int j = 0; j < 4; j++) {
                    fma2(acc[i][j], a4[i].x, b4[j].x);
                    fma2(acc[i][j], a4[i].y, b4[j].y);
                }
        }
        __syncthreads();
    }
#pragma unroll
    for (int i = 0; i < 8; i++) {
#pragma unroll
        for (int j = 0; j < 4; j++) {
            F2U u; u.u = acc[i][j];
            int n = n0 + tx * 4 + j;
            C[(size_t)(m0 + ty * 8 + i) * N + n] = u.f.x + u.f.y + bias[n];
        }
    }
}

// ---------------- persistent recurrence (512 thr, split-K 16) ----------
// 128 CTAs = 32 col-groups x 4 batch-quarters. CTA keeps Wh[:, h0..h0+31]
// in SMEM for all steps. 16 warps; warp = one 64-wide k-slice, stages its
// own s slice with __syncwarp. Thread tile 4 cols x 4 rows. Split-K reduce
// via a conflict-free bit-packed layout; each thread finalizes 1 output.
__global__ void __launch_bounds__(512, 1) k_rnn(const float* __restrict__ Wh) {
    extern __shared__ __align__(16) float smem[];
    float* wh  = smem;                 // [CPC][WST]
    float* ssm = smem + CPC * WST;     // [RPC][WST]; aliased as reduce buffer

    int tid  = threadIdx.x;
    int lane = tid & 31;
    int ks   = tid >> 5;               // warp id = k-slice 0..15
    int cgrp = tid & 7;                // col sub-index 0..7
    int bg   = (tid >> 3) & 3;         // row sub-index 0..3
    int cta  = blockIdx.x;
    int cg   = cta >> 2;               // 0..31
    int bq   = cta & 3;                // 0..3
    int h0   = cg * CPC;
    int b0   = bq * RPC;
    int k0s  = ks * KPT;

    // load Wh slice, transposed to [col][k]
    for (int idx = tid; idx < CPC * H_; idx += 512) {
        int k = idx >> 5, c = idx & 31;
        wh[c * WST + k] = Wh[(size_t)k * H_ + h0 + c];
    }
    __syncthreads();

    const float* wp[4];
    const float* sp[4];
#pragma unroll
    for (int i = 0; i < 4; i++) wp[i] = wh + (cgrp + 8 * i) * WST + k0s;
#pragma unroll
    for (int j = 0; j < 4; j++) sp[j] = ssm + (bg + 4 * j) * WST + k0s;

    // output this thread finalizes (bit-packed decode)
    int fcol = (tid & 7) + 8 * ((tid >> 5) & 3);
    int frow = ((tid >> 3) & 3) + 4 * ((tid >> 7) & 3);

    for (int t = 0; t < T_; t++) {
        const float* cur = g_s[t & 1];
        float* nxt = g_s[(t + 1) & 1];

        // stage this warp's own k-slice: 16 rows x 64 k (L2, bypass L1)
#pragma unroll
        for (int l = 0; l < 8; l++) {
            int idx = lane + 32 * l;          // 0..255 float4s
            int r = idx >> 4, q = (idx & 15) * 4;
            float4 v = __ldcg(reinterpret_cast<const float4*>(
                &cur[(size_t)(b0 + r) * H_ + k0s + q]));
            *reinterpret_cast<float4*>(&ssm[r * WST + k0s + q]) = v;
        }
        __syncwarp();

        // prefetch pre value for the output this thread finalizes
        float p0 = __ldcs(&g_pre[((size_t)t * B_ + b0 + frow) * H_ + h0 + fcol]);

        ull acc[4][4];
#pragma unroll
        for (int i = 0; i < 4; i++)
#pragma unroll
            for (int j = 0; j < 4; j++) acc[i][j] = 0ull;

#pragma unroll 2
        for (int kk = 0; kk < KPT; kk += 4) {
            ulonglong2 w[4], s[4];
#pragma unroll
            for (int i = 0; i < 4; i++)
                w[i] = *reinterpret_cast<const ulonglong2*>(wp[i] + kk);
#pragma unroll
            for (int j = 0; j < 4; j++)
                s[j] = *reinterpret_cast<const ulonglong2*>(sp[j] + kk);
#pragma unroll
            for (int i = 0; i < 4; i++)
#pragma unroll
                for (int j = 0; j < 4; j++) {
                    fma2(acc[i][j], w[i].x, s[j].x);
                    fma2(acc[i][j], w[i].y, s[j].y);
                }
        }

        // split-K reduce; bit-packed index -> conflict-free STS and LDS
        __syncthreads();                       // all warps done reading ssm
        float* red = ssm;
#pragma unroll
        for (int i = 0; i < 4; i++)
#pragma unroll
            for (int j = 0; j < 4; j++) {
                F2U u; u.u = acc[i][j];
                int out = cgrp | (bg << 3) | (i << 5) | (j << 7);
                red[ks * RST + out] = u.f.x + u.f.y;
            }
        __syncthreads();

        float ssum = 0.f;
#pragma unroll
        for (int q = 0; q < KSPL; q++) ssum += red[q * RST + tid];

        float v0 = tanhf(p0 + ssum);
        int hb = h0 + fcol, bb = b0 + frow;
        __stcs(&g_states[((size_t)bb * T_ + t) * H_ + hb], v0);
        __stcg(&nxt[bb * H_ + hb], v0);

        // grid barrier
        __syncthreads();
        if (tid == 0) {
            __threadfence();
            atomicAdd(&g_bar, 1u);
            unsigned target = (unsigned)(t + 1) * GRC;
            while (*((volatile unsigned*)&g_bar) < target) { }
        }
        __syncthreads();
    }
}

// ---------------- launch ----------------
extern "C" void kernel_launch(void* const* d_in, const int* in_sizes, int n_in,
                              void* d_out, int out_size) {
    const float* x    = (const float*)d_in[0];
    const float* Wx   = (const float*)d_in[1];
    const float* Wh   = (const float*)d_in[2];
    const float* bias = (const float*)d_in[3];
    const float* Wout = (const float*)d_in[4];
    const float* bout = (const float*)d_in[5];
    float* out = (float*)d_out;

    float *pXT, *pPre, *pStates;
    cudaGetSymbolAddress((void**)&pXT, g_xT);
    cudaGetSymbolAddress((void**)&pPre, g_pre);
    cudaGetSymbolAddress((void**)&pStates, g_states);

    int rnn_smem = (CPC + RPC) * WST * (int)sizeof(float);   // 197376 B
    cudaFuncSetAttribute(k_rnn, cudaFuncAttributeMaxDynamicSharedMemorySize, rnn_smem);

    k_init<<<64, 256>>>();
    k_transpose<<<dim3(T_ / 32, F_ / 32, B_), dim3(32, 8)>>>(x);
    // pre = xT @ Wx + b     (M=65536, N=1024, K=256)
    k_sgemm<<<dim3(H_ / 64, (T_ * B_) / 128), 256>>>(pXT, Wx, bias, pPre,
                                                     T_ * B_, H_, F_);
    // recurrence -> g_states
    k_rnn<<<GRC, 512, rnn_smem>>>(Wh);
    // out = states @ Wout + bout   (M=65536, N=512, K=1024)
    k_sgemm<<<dim3(O_ / 64, (B_ * T_) / 128), 256>>>(pStates, Wout, bout, out,
                                                     B_ * T_, O_, H_);
}

// round 7
// speedup vs baseline: 1.1009x; 1.1009x over previous
#include <cuda_runtime.h>

#define B_  64
#define F_  256
#define T_  1024
#define H_  1024
#define O_  512

#define GRC   128         // recurrence CTAs (one wave)
#define CPC   32          // cols per CTA
#define RPC   16          // batch rows per CTA
#define KSPL  32          // k-split (half-warp = one 32-wide k-slice)
#define KPT   32          // k per slice
#define WST   1028        // wh stride (floats): 16B aligned, bank offset 4
#define SST   1028        // s stride
#define RST   520         // reduce row stride (per k-slice)
#define SSMF  16640       // ssm region floats = max(16*SST, KSPL*RST)

// -------- scratch (no allocations allowed; device globals) --------
__device__ float g_xT[(size_t)T_ * B_ * F_];
__device__ float g_pre[(size_t)T_ * B_ * H_];       // (T,B,H)
__device__ float g_states[(size_t)B_ * T_ * H_];    // (B,T,H)
__device__ float g_s[2][B_ * H_];
__device__ unsigned g_bar;

typedef unsigned long long ull;
union F2U { ull u; float2 f; };

__device__ __forceinline__ void fma2(ull& d, ull a, ull b) {
    asm("fma.rn.f32x2 %0, %1, %2, %0;" : "+l"(d) : "l"(a), "l"(b));
}

// ---------------- init: zero state buffer 0 + barrier ----------------
__global__ void k_init() {
    int idx = blockIdx.x * blockDim.x + threadIdx.x;
    for (int i = idx; i < B_ * H_; i += gridDim.x * blockDim.x) g_s[0][i] = 0.0f;
    if (idx == 0) g_bar = 0u;
}

// ---------------- transpose x(B,F,T) -> xT(T*B, F) ----------------
__global__ void k_transpose(const float* __restrict__ x) {
    __shared__ float tile[32][33];
    int b  = blockIdx.z;
    int f0 = blockIdx.y * 32;
    int t0 = blockIdx.x * 32;
    int tx = threadIdx.x, ty = threadIdx.y;     // 32 x 8
#pragma unroll
    for (int i = 0; i < 4; i++) {
        int f = f0 + ty + i * 8;
        tile[ty + i * 8][tx] = x[((size_t)b * F_ + f) * T_ + t0 + tx];
    }
    __syncthreads();
#pragma unroll
    for (int i = 0; i < 4; i++) {
        int t = t0 + ty + i * 8;
        g_xT[((size_t)t * B_ + b) * F_ + f0 + tx] = tile[tx][ty + i * 8];
    }
}

// ---------------- fp32 SGEMM (round-4 proven version) ----------------
__global__ void __launch_bounds__(256) k_sgemm(const float* __restrict__ A,
                                               const float* __restrict__ Bm,
                                               const float* __restrict__ bias,
                                               float* __restrict__ C,
                                               int M, int N, int K) {
    __shared__ __align__(16) float As[128 * 18];
    __shared__ __align__(16) float Bs[64 * 18];
    int tid = threadIdx.x;
    int tx = tid & 15, ty = tid >> 4;
    int n0 = blockIdx.x * 64;
    int m0 = blockIdx.y * 128;

    ull acc[8][4];
#pragma unroll
    for (int i = 0; i < 8; i++)
#pragma unroll
        for (int j = 0; j < 4; j++) acc[i][j] = 0ull;

    for (int k0 = 0; k0 < K; k0 += 16) {
#pragma unroll
        for (int l = 0; l < 2; l++) {
            int j = tid + l * 256;
            int row = j >> 2, kq = (j & 3) * 4;
            float4 v = *reinterpret_cast<const float4*>(&A[(size_t)(m0 + row) * K + k0 + kq]);
            As[row * 18 + kq + 0] = v.x;
            As[row * 18 + kq + 1] = v.y;
            As[row * 18 + kq + 2] = v.z;
            As[row * 18 + kq + 3] = v.w;
        }
        {
            int k = tid >> 4, nq = (tid & 15) * 4;
            float4 v = *reinterpret_cast<const float4*>(&Bm[(size_t)(k0 + k) * N + n0 + nq]);
            Bs[(nq + 0) * 18 + k] = v.x;
            Bs[(nq + 1) * 18 + k] = v.y;
            Bs[(nq + 2) * 18 + k] = v.z;
            Bs[(nq + 3) * 18 + k] = v.w;
        }
        __syncthreads();
#pragma unroll
        for (int p = 0; p < 8; p++) {
            ull a2[8], b2[4];
#pragma unroll
            for (int i = 0; i < 8; i++)
                a2[i] = *reinterpret_cast<const ull*>(&As[(ty * 8 + i) * 18 + p * 2]);
#pragma unroll
            for (int j = 0; j < 4; j++)
                b2[j] = *reinterpret_cast<const ull*>(&Bs[(tx * 4 + j) * 18 + p * 2]);
#pragma unroll
            for (int i = 0; i < 8; i++)
#pragma unroll
                for (int j = 0; j < 4; j++) fma2(acc[i][j], a2[i], b2[j]);
        }
        __syncthreads();
    }
#pragma unroll
    for (int i = 0; i < 8; i++) {
#pragma unroll
        for (int j = 0; j < 4; j++) {
            F2U u; u.u = acc[i][j];
            int n = n0 + tx * 4 + j;
            C[(size_t)(m0 + ty * 8 + i) * N + n] = u.f.x + u.f.y + bias[n];
        }
    }
}

// ---------------- persistent recurrence (8x4 tile, split-K 32) ----------
// 128 CTAs = 32 col-groups x 4 batch-quarters. Wh[:, h0..h0+31] in SMEM.
// 512 thr; half-warp = one 32-wide k-slice (warp stages its contiguous
// 64-k range with __syncwarp). Thread tile 8 cols x 4 rows -> 3 B of SMEM
// per fma2 (crossbar 6144 cyc/step vs FMA floor 4096).
__global__ void __launch_bounds__(512, 1) k_rnn(const float* __restrict__ Wh) {
    extern __shared__ __align__(16) float smem[];
    float* wh  = smem;                 // [CPC][WST]
    float* ssm = smem + CPC * WST;     // [RPC][SST]; aliased as reduce buffer

    int tid   = threadIdx.x;
    int lane  = tid & 31;
    int wid   = tid >> 5;              // warp 0..15
    int slice = tid >> 4;              // k-slice 0..31
    int sp    = tid & 15;              // spatial id within slice
    int cgrp  = sp & 3;                // col sub-index 0..3  (col = cgrp+4i)
    int bg    = (sp >> 2) & 3;         // row sub-index 0..3  (row = bg+4j)
    int cta   = blockIdx.x;
    int cg    = cta >> 2;
    int bq    = cta & 3;
    int h0    = cg * CPC;
    int b0    = bq * RPC;
    int k0s   = slice * KPT;
    int kw    = wid * 64;              // warp's staged k range

    // load Wh slice, transposed to [col][k]
    for (int idx = tid; idx < CPC * H_; idx += 512) {
        int k = idx >> 5, c = idx & 31;
        wh[c * WST + k] = Wh[(size_t)k * H_ + h0 + c];
    }
    __syncthreads();

    const float* wb = wh + cgrp * WST + k0s;   // + i*4*WST (imm offsets)
    const float* sb = ssm + bg * SST + k0s;    // + j*4*SST

    // output this thread finalizes: oid == tid (col = tid&31, row = tid>>5)
    int fcol = tid & 31;
    int frow = tid >> 5;

    for (int t = 0; t < T_; t++) {
        const float* cur = g_s[t & 1];
        float* nxt = g_s[(t + 1) & 1];

        // stage warp's 16 rows x 64 k (L2, bypass L1)
#pragma unroll
        for (int l = 0; l < 8; l++) {
            int idx = lane + 32 * l;          // 0..255 float4s
            int r = idx >> 4, q = (idx & 15) * 4;
            float4 v = __ldcg(reinterpret_cast<const float4*>(
                &cur[(size_t)(b0 + r) * H_ + kw + q]));
            *reinterpret_cast<float4*>(&ssm[r * SST + kw + q]) = v;
        }
        __syncwarp();

        float p0 = __ldcs(&g_pre[((size_t)t * B_ + b0 + frow) * H_ + h0 + fcol]);

        ull acc[8][4];
#pragma unroll
        for (int i = 0; i < 8; i++)
#pragma unroll
            for (int j = 0; j < 4; j++) acc[i][j] = 0ull;

#pragma unroll 2
        for (int kk = 0; kk < KPT; kk += 4) {
            ulonglong2 s[4];
#pragma unroll
            for (int j = 0; j < 4; j++)
                s[j] = *reinterpret_cast<const ulonglong2*>(sb + j * 4 * SST + kk);
#pragma unroll
            for (int i = 0; i < 8; i++) {
                ulonglong2 w = *reinterpret_cast<const ulonglong2*>(wb + i * 4 * WST + kk);
#pragma unroll
                for (int j = 0; j < 4; j++) {
                    fma2(acc[i][j], w.x, s[j].x);
                    fma2(acc[i][j], w.y, s[j].y);
                }
            }
        }

        // split-K reduce through ssm alias: red[slice][col + 32*row]
        __syncthreads();                       // all compute reads of ssm done
        float* red = ssm;
#pragma unroll
        for (int i = 0; i < 8; i++)
#pragma unroll
            for (int j = 0; j < 4; j++) {
                F2U u; u.u = acc[i][j];
                int out = (cgrp + 4 * i) + 32 * (bg + 4 * j);
                red[slice * RST + out] = u.f.x + u.f.y;
            }
        __syncthreads();

        float ssum = 0.f;
#pragma unroll
        for (int q = 0; q < KSPL; q++) ssum += red[q * RST + tid];

        float v0 = tanhf(p0 + ssum);
        int hb = h0 + fcol, bb = b0 + frow;
        __stcs(&g_states[((size_t)bb * T_ + t) * H_ + hb], v0);
        __stcg(&nxt[bb * H_ + hb], v0);

        // grid barrier
        __syncthreads();
        if (tid == 0) {
            __threadfence();
            atomicAdd(&g_bar, 1u);
            unsigned target = (unsigned)(t + 1) * GRC;
            while (*((volatile unsigned*)&g_bar) < target) { }
        }
        __syncthreads();
    }
}

// ---------------- launch ----------------
extern "C" void kernel_launch(void* const* d_in, const int* in_sizes, int n_in,
                              void* d_out, int out_size) {
    const float* x    = (const float*)d_in[0];
    const float* Wx   = (const float*)d_in[1];
    const float* Wh   = (const float*)d_in[2];
    const float* bias = (const float*)d_in[3];
    const float* Wout = (const float*)d_in[4];
    const float* bout = (const float*)d_in[5];
    float* out = (float*)d_out;

    float *pXT, *pPre, *pStates;
    cudaGetSymbolAddress((void**)&pXT, g_xT);
    cudaGetSymbolAddress((void**)&pPre, g_pre);
    cudaGetSymbolAddress((void**)&pStates, g_states);

    int rnn_smem = (CPC * WST + SSMF) * (int)sizeof(float);   // 198144 B
    cudaFuncSetAttribute(k_rnn, cudaFuncAttributeMaxDynamicSharedMemorySize, rnn_smem);

    k_init<<<64, 256>>>();
    k_transpose<<<dim3(T_ / 32, F_ / 32, B_), dim3(32, 8)>>>(x);
    // pre = xT @ Wx + b     (M=65536, N=1024, K=256)
    k_sgemm<<<dim3(H_ / 64, (T_ * B_) / 128), 256>>>(pXT, Wx, bias, pPre,
                                                     T_ * B_, H_, F_);
    // recurrence -> g_states
    k_rnn<<<GRC, 512, rnn_smem>>>(Wh);
    // out = states @ Wout + bout   (M=65536, N=512, K=1024)
    k_sgemm<<<dim3(O_ / 64, (B_ * T_) / 128), 256>>>(pStates, Wout, bout, out,
                                                     B_ * T_, O_, H_);
}